// round 6
// baseline (speedup 1.0000x reference)
#include <cuda_runtime.h>
#include <math.h>

// ---------------- scratch (device globals; no allocation) ----------------
__device__ float g_h0[1024];
__device__ float g_h1[1024];
__device__ float g_h2[1024];
__device__ float g_acc_qkv[5120];      // [q:8*hd][k:hd][v:hd]
__device__ float g_scores[8 * 2048];   // [h][j]
__device__ float g_attn_part[16 * 4096]; // [chunk][h*hd+d]
__device__ float g_acc_o[1024];
__device__ float g_acc_gu[8192];       // [g:4096][u:4096]
__device__ float g_acc_mlp[1024];
__device__ float g_acc_pg[256];
__device__ float g_acc_pli[1024];
__device__ float g_kcur[15][512];
__device__ float g_vcur[15][512];

// ---------------- helpers ----------------
__device__ __forceinline__ float blockReduceSum(float v, float* sred) {
    int tid = threadIdx.x;
    #pragma unroll
    for (int o = 16; o; o >>= 1) v += __shfl_xor_sync(0xffffffff, v, o);
    if ((tid & 31) == 0) sred[tid >> 5] = v;
    __syncthreads();
    if (tid == 0) {
        float t = sred[0];
        #pragma unroll
        for (int i = 1; i < 8; i++) t += sred[i];
        sred[0] = t;
    }
    __syncthreads();
    float r = sred[0];
    __syncthreads();
    return r;
}

__device__ __forceinline__ float blockReduceMax(float v, float* sred) {
    int tid = threadIdx.x;
    #pragma unroll
    for (int o = 16; o; o >>= 1) v = fmaxf(v, __shfl_xor_sync(0xffffffff, v, o));
    if ((tid & 31) == 0) sred[tid >> 5] = v;
    __syncthreads();
    if (tid == 0) {
        float t = sred[0];
        #pragma unroll
        for (int i = 1; i < 8; i++) t = fmaxf(t, sred[i]);
        sred[0] = t;
    }
    __syncthreads();
    float r = sred[0];
    __syncthreads();
    return r;
}

__device__ __forceinline__ float gelu_tanh(float x) {
    float x3 = x * x * x;
    return 0.5f * x * (1.f + tanhf(0.7978845608028654f * (x + 0.044715f * x3)));
}

// ---------------- embed ----------------
__global__ __launch_bounds__(256) void k_embed(const float* __restrict__ embed,
                                               const float* __restrict__ img,
                                               const int* __restrict__ ids) {
    __shared__ float sred[9];
    int tid = threadIdx.x;
    int id = ids[0];
    float iv[4];
    float sa = 0.f;
    #pragma unroll
    for (int i = 0; i < 4; i++) { iv[i] = img[tid + i * 256]; sa += fabsf(iv[i]); }
    sa = blockReduceSum(sa, sred);
    bool isimg = sa > 0.f;
    const float* er = embed + (size_t)id * 1024;
    #pragma unroll
    for (int i = 0; i < 4; i++) {
        int idx = tid + i * 256;
        g_h0[idx] = isimg ? iv[i] : er[idx] * 32.0f; // sqrt(1024)=32
    }
    for (int z = tid; z < 5120; z += 256) g_acc_qkv[z] = 0.f;
}

// ---------------- K1: QKV gemv (+ finish previous layer's h) ----------------
__global__ __launch_bounds__(256) void k_qkv(const float* __restrict__ Wq,
                                             const float* __restrict__ Wk,
                                             const float* __restrict__ Wv,
                                             const float* __restrict__ ln_in,
                                             const float* __restrict__ ln_ppli,
                                             const float* __restrict__ lscal,
                                             int l, int hd) {
    __shared__ float xs[1024];
    __shared__ float sred[9];
    int tid = threadIdx.x;
    float h0v[4];
    if (l == 0) {
        #pragma unroll
        for (int i = 0; i < 4; i++) h0v[i] = g_h0[tid + i * 256];
    } else {
        const float* lw = ln_ppli + (size_t)(l - 1) * 1024;
        float pv[4]; float ss = 0.f;
        #pragma unroll
        for (int i = 0; i < 4; i++) { pv[i] = g_acc_pli[tid + i * 256]; ss += pv[i] * pv[i]; }
        ss = blockReduceSum(ss, sred);
        float r = rsqrtf(ss / 1024.f + 1e-6f);
        float sc = lscal[l - 1];
        #pragma unroll
        for (int i = 0; i < 4; i++) {
            int idx = tid + i * 256;
            h0v[i] = (g_h2[idx] + pv[i] * r * (1.f + lw[idx])) * sc;
        }
        if (blockIdx.x == 0 && blockIdx.y == 0)
            #pragma unroll
            for (int i = 0; i < 4; i++) g_h0[tid + i * 256] = h0v[i];
    }
    {
        float ss = 0.f;
        #pragma unroll
        for (int i = 0; i < 4; i++) ss += h0v[i] * h0v[i];
        ss = blockReduceSum(ss, sred);
        float r = rsqrtf(ss / 1024.f + 1e-6f);
        const float* lw = ln_in + (size_t)l * 1024;
        #pragma unroll
        for (int i = 0; i < 4; i++) { int idx = tid + i * 256; xs[idx] = h0v[i] * r * (1.f + lw[idx]); }
    }
    __syncthreads();

    int o = blockIdx.x * 256 + tid;
    int qsize = 8 * hd;
    int lhd = (hd == 512) ? 9 : 8;
    const float* wbase; int stride;
    if (o < qsize) {
        int hh = o >> lhd; int d = o & (hd - 1);
        wbase = Wq + (size_t)l * 1024 * 4096 + hh * 512 + d; stride = 4096;
    } else if (o < qsize + hd) {
        wbase = Wk + (size_t)l * 1024 * 512 + (o - qsize); stride = 512;
    } else {
        wbase = Wv + (size_t)l * 1024 * 512 + (o - qsize - hd); stride = 512;
    }
    int e0 = blockIdx.y * 128;
    const float* wp = wbase + (size_t)e0 * stride;
    float acc = 0.f;
    #pragma unroll 16
    for (int e = 0; e < 128; e++) { acc += xs[e0 + e] * wp[0]; wp += stride; }
    atomicAdd(&g_acc_qkv[o], acc);
}

// ---------------- K2: finalize q/k/v (rms+rope) + scores ----------------
__global__ __launch_bounds__(256) void k_scores(const float* __restrict__ kv,
                                                const float* __restrict__ qn_w,
                                                const float* __restrict__ kn_w,
                                                const float* __restrict__ cost,
                                                const float* __restrict__ sint,
                                                const int* __restrict__ pos_ids,
                                                int l, int hd) {
    __shared__ float qf[8 * 512];
    __shared__ float kc[512];
    __shared__ float vc[512];
    __shared__ float sred[9];
    int tid = threadIdx.x, wid = tid >> 5, lane = tid & 31;
    int pos = pos_ids[0];
    int half = hd >> 1;
    int lhd = (hd == 512) ? 9 : 8;
    const float* cr = cost + (size_t)pos * hd;
    const float* sr = sint + (size_t)pos * hd;

    // zero acc_o for K5's atomics
    { int gt = blockIdx.x * 256 + tid; if (gt < 1024) g_acc_o[gt] = 0.f; }

    // q rms per head (warp wid -> head wid)
    {
        const float* qraw = g_acc_qkv + (size_t)wid * hd;
        float ss = 0.f;
        for (int i = lane; i < hd; i += 32) { float v = qraw[i]; ss += v * v; }
        #pragma unroll
        for (int o = 16; o; o >>= 1) ss += __shfl_xor_sync(0xffffffff, ss, o);
        float r = rsqrtf(ss / (float)hd + 1e-6f);
        const float* qw = qn_w + (size_t)l * 512;
        for (int i = lane; i < hd; i += 32) qf[wid * hd + i] = qraw[i] * r * (1.f + qw[i]);
    }
    // k rms
    {
        float ss = 0.f;
        for (int i = tid; i < hd; i += 256) { float v = g_acc_qkv[8 * hd + i]; ss += v * v; }
        ss = blockReduceSum(ss, sred);
        float r = rsqrtf(ss / (float)hd + 1e-6f);
        const float* kw = kn_w + (size_t)l * 512;
        for (int i = tid; i < hd; i += 256) kc[i] = g_acc_qkv[8 * hd + i] * r * (1.f + kw[i]);
    }
    // v norm
    {
        float ss = 0.f;
        for (int i = tid; i < hd; i += 256) { float v = g_acc_qkv[9 * hd + i]; ss += v * v; }
        ss = blockReduceSum(ss, sred);
        float r = rsqrtf(ss / (float)hd + 1e-6f);
        for (int i = tid; i < hd; i += 256) vc[i] = g_acc_qkv[9 * hd + i] * r;
    }
    __syncthreads();
    // rope q,k (read pairs to regs, sync, write)
    float tq[16]; float tk[2];
    int nq = (8 * hd) / 256;  // 8 or 16
    int nk = hd / 256;        // 1 or 2
    for (int i = 0; i < nq; i++) {
        int idx = tid + i * 256;
        int h = idx >> lhd; int d = idx & (hd - 1);
        float x = qf[idx];
        float rot = (d < half) ? -qf[h * hd + d + half] : qf[h * hd + d - half];
        tq[i] = x * cr[d] + rot * sr[d];
    }
    for (int i = 0; i < nk; i++) {
        int d = tid + i * 256;
        float x = kc[d];
        float rot = (d < half) ? -kc[d + half] : kc[d - half];
        tk[i] = x * cr[d] + rot * sr[d];
    }
    __syncthreads();
    for (int i = 0; i < nq; i++) qf[tid + i * 256] = tq[i];
    for (int i = 0; i < nk; i++) kc[tid + i * 256] = tk[i];
    __syncthreads();
    if (blockIdx.x == 0) {
        for (int i = 0; i < nk; i++) {
            g_kcur[l][tid + i * 256] = kc[tid + i * 256];
            g_vcur[l][tid + i * 256] = vc[tid + i * 256];
        }
    }
    // scores: warp wid handles j = blockIdx.x*8 + wid
    int j = blockIdx.x * 8 + wid;
    if (j <= pos) {
        const float* Kr = (j == pos) ? kc : (kv + ((size_t)l * 2048 + j) * 512);
        float a[8] = {0, 0, 0, 0, 0, 0, 0, 0};
        for (int i = lane; i < hd; i += 32) {
            float kvv = Kr[i];
            #pragma unroll
            for (int h = 0; h < 8; h++) a[h] += qf[h * hd + i] * kvv;
        }
        #pragma unroll
        for (int h = 0; h < 8; h++) {
            float t = a[h];
            #pragma unroll
            for (int o = 16; o; o >>= 1) t += __shfl_xor_sync(0xffffffff, t, o);
            if (lane == 0) g_scores[h * 2048 + j] = t;
        }
    }
}

// ---------------- K4: softmax + weighted V (partials per j-chunk) ----------------
__global__ __launch_bounds__(256) void k_attnv(const float* __restrict__ kv,
                                               const int* __restrict__ pos_ids,
                                               int l, int hd) {
    __shared__ float ps[128];
    __shared__ float sred[9];
    int tid = threadIdx.x;
    int h = blockIdx.y;
    int pos = pos_ids[0];
    const float* sc = g_scores + (size_t)h * 2048;
    // zero acc_gu for K6
    { int gt = (blockIdx.y * gridDim.x + blockIdx.x) * 256 + tid; if (gt < 8192) g_acc_gu[gt] = 0.f; }
    // stats
    float mx = -1e30f;
    for (int j = tid; j <= pos; j += 256) mx = fmaxf(mx, sc[j]);
    mx = blockReduceMax(mx, sred);
    float se = 0.f;
    for (int j = tid; j <= pos; j += 256) se += __expf(sc[j] - mx);
    se = blockReduceSum(se, sred);
    float inv = 1.f / se;

    int j0 = blockIdx.x * 128;
    if (tid < 128) {
        int j = j0 + tid;
        ps[tid] = (j < pos) ? __expf(sc[j] - mx) * inv : 0.f;
    }
    __syncthreads();
    int jend = pos < j0 + 128 ? pos : j0 + 128; // exclusive bound over cache rows (< pos)
    int nj = jend - j0; if (nj < 0) nj = 0;

    const float* Vb = kv + ((size_t)(15 + l) * 2048 + j0) * 512;
    int nd = hd >> 8;  // 1 or 2
    int d0 = tid, d1 = tid + 256;
    float acc0 = 0.f, acc1 = 0.f;
    #pragma unroll 4
    for (int jj = 0; jj < nj; jj++) {
        float p = ps[jj];
        const float* vr = Vb + (size_t)jj * 512;
        acc0 += p * vr[d0];
        if (nd == 2) acc1 += p * vr[d1];
    }
    if (pos >= j0 && pos < j0 + 128) {
        float pp = __expf(sc[pos] - mx) * inv;
        acc0 += pp * g_vcur[l][d0];
        if (nd == 2) acc1 += pp * g_vcur[l][d1];
    }
    float* op = g_attn_part + (size_t)blockIdx.x * 4096;
    op[h * hd + d0] = acc0;
    if (nd == 2) op[h * hd + d1] = acc1;
}

// ---------------- K5: Wo gemv ----------------
template <int CH>
__global__ __launch_bounds__(256) void k_wo(const float* __restrict__ Wo, int l, int hd) {
    __shared__ float xs[4096];
    int tid = threadIdx.x;
    int N = 8 * hd;
    for (int i = tid; i < N; i += 256) {
        float s = 0.f;
        #pragma unroll
        for (int c = 0; c < 16; c++) s += g_attn_part[c * 4096 + i];
        xs[i] = s;
    }
    __syncthreads();
    int o = blockIdx.x * 256 + tid;
    int i0 = blockIdx.y * CH;
    int lhd = (hd == 512) ? 9 : 8;
    int row0 = (i0 >> lhd) * 512 + (i0 & (hd - 1));
    const float* wp = Wo + (size_t)l * 8 * 512 * 1024 + (size_t)row0 * 1024 + o;
    float acc = 0.f;
    #pragma unroll 16
    for (int i = 0; i < CH; i++) { acc += xs[i0 + i] * wp[0]; wp += 1024; }
    atomicAdd(&g_acc_o[o], acc);
    int gt = (blockIdx.y * gridDim.x + blockIdx.x) * 256 + tid;
    if (gt < 1024) g_acc_mlp[gt] = 0.f;
}

// ---------------- K6: FF gate+up gemv ----------------
__global__ __launch_bounds__(256) void k_ff1(const float* __restrict__ Wg,
                                             const float* __restrict__ Wu,
                                             const float* __restrict__ ln_pa,
                                             const float* __restrict__ ln_pff, int l) {
    __shared__ float xs[1024];
    __shared__ float sred[9];
    int tid = threadIdx.x;
    float ov[4], h1v[4];
    float ss = 0.f;
    #pragma unroll
    for (int i = 0; i < 4; i++) { ov[i] = g_acc_o[tid + i * 256]; ss += ov[i] * ov[i]; }
    ss = blockReduceSum(ss, sred);
    float r = rsqrtf(ss / 1024.f + 1e-6f);
    const float* wpa = ln_pa + (size_t)l * 1024;
    #pragma unroll
    for (int i = 0; i < 4; i++) { int idx = tid + i * 256; h1v[i] = g_h0[idx] + ov[i] * r * (1.f + wpa[idx]); }
    if (blockIdx.x == 0 && blockIdx.y == 0)
        #pragma unroll
        for (int i = 0; i < 4; i++) g_h1[tid + i * 256] = h1v[i];
    float s2 = 0.f;
    #pragma unroll
    for (int i = 0; i < 4; i++) s2 += h1v[i] * h1v[i];
    s2 = blockReduceSum(s2, sred);
    float r2 = rsqrtf(s2 / 1024.f + 1e-6f);
    const float* wpf = ln_pff + (size_t)l * 1024;
    #pragma unroll
    for (int i = 0; i < 4; i++) { int idx = tid + i * 256; xs[idx] = h1v[i] * r2 * (1.f + wpf[idx]); }
    __syncthreads();

    int o = blockIdx.x * 256 + tid; // 0..8191
    const float* wb = (o < 4096) ? (Wg + (size_t)l * 1024 * 4096 + o)
                                 : (Wu + (size_t)l * 1024 * 4096 + (o - 4096));
    int e0 = blockIdx.y * 256;
    const float* wp = wb + (size_t)e0 * 4096;
    float acc = 0.f;
    #pragma unroll 16
    for (int e = 0; e < 256; e++) { acc += xs[e0 + e] * wp[0]; wp += 4096; }
    atomicAdd(&g_acc_gu[o], acc);
    int gt = (blockIdx.y * gridDim.x + blockIdx.x) * 256 + tid;
    if (gt < 256) g_acc_pg[gt] = 0.f;
}

// ---------------- K7: FF down gemv ----------------
__global__ __launch_bounds__(256) void k_wd(const float* __restrict__ Wd, int l) {
    __shared__ float xs[4096];
    int tid = threadIdx.x;
    for (int i = tid; i < 4096; i += 256) {
        float gv = g_acc_gu[i], uv = g_acc_gu[4096 + i];
        xs[i] = gelu_tanh(gv) * uv;
    }
    __syncthreads();
    int o = blockIdx.x * 256 + tid;
    int i0 = blockIdx.y * 128;
    const float* wp = Wd + (size_t)l * 4096 * 1024 + (size_t)i0 * 1024 + o;
    float acc = 0.f;
    #pragma unroll 16
    for (int i = 0; i < 128; i++) { acc += xs[i0 + i] * wp[0]; wp += 1024; }
    atomicAdd(&g_acc_mlp[o], acc);
    int gt = (blockIdx.y * gridDim.x + blockIdx.x) * 256 + tid;
    if (gt < 1024) g_acc_pli[gt] = 0.f;
}

// ---------------- K8: PLI gate gemv ----------------
__global__ __launch_bounds__(256) void k_pli1(const float* __restrict__ Wpg,
                                              const float* __restrict__ ln_postff, int l) {
    __shared__ float xs[1024];
    __shared__ float sred[9];
    int tid = threadIdx.x;
    float mv[4];
    float ss = 0.f;
    #pragma unroll
    for (int i = 0; i < 4; i++) { mv[i] = g_acc_mlp[tid + i * 256]; ss += mv[i] * mv[i]; }
    ss = blockReduceSum(ss, sred);
    float r = rsqrtf(ss / 1024.f + 1e-6f);
    const float* w = ln_postff + (size_t)l * 1024;
    #pragma unroll
    for (int i = 0; i < 4; i++) {
        int idx = tid + i * 256;
        float h2 = g_h1[idx] + mv[i] * r * (1.f + w[idx]);
        xs[idx] = h2;
        if (blockIdx.y == 0) g_h2[idx] = h2;  // blockIdx.x is always 0
    }
    __syncthreads();
    int o = tid;
    int e0 = blockIdx.y * 64;
    const float* wp = Wpg + (size_t)l * 1024 * 256 + (size_t)e0 * 256 + o;
    float acc = 0.f;
    #pragma unroll 16
    for (int e = 0; e < 64; e++) { acc += xs[e0 + e] * wp[0]; wp += 256; }
    atomicAdd(&g_acc_pg[o], acc);
    int gt = blockIdx.y * 256 + tid;
    for (int z = gt; z < 5120; z += gridDim.y * 256) g_acc_qkv[z] = 0.f;
}

// ---------------- K9: PLI proj gemv ----------------
__global__ __launch_bounds__(256) void k_pli2(const float* __restrict__ Wpp,
                                              const float* __restrict__ plc, int l) {
    __shared__ float xs[256];
    int tid = threadIdx.x;
    xs[tid] = gelu_tanh(g_acc_pg[tid]) * plc[(size_t)l * 256 + tid];
    __syncthreads();
    int o = blockIdx.x * 256 + tid;
    int e0 = blockIdx.y * 32;
    const float* wp = Wpp + (size_t)l * 256 * 1024 + (size_t)e0 * 1024 + o;
    float acc = 0.f;
    #pragma unroll
    for (int e = 0; e < 32; e++) { acc += xs[e0 + e] * wp[0]; wp += 1024; }
    atomicAdd(&g_acc_pli[o], acc);
}

// ---------------- final h ----------------
__global__ __launch_bounds__(256) void k_final(float* __restrict__ out,
                                               const float* __restrict__ ln_ppli,
                                               const float* __restrict__ lscal) {
    __shared__ float sred[9];
    int tid = threadIdx.x;
    const float* w = ln_ppli + (size_t)14 * 1024;
    float pv[4]; float ss = 0.f;
    #pragma unroll
    for (int i = 0; i < 4; i++) { pv[i] = g_acc_pli[tid + i * 256]; ss += pv[i] * pv[i]; }
    ss = blockReduceSum(ss, sred);
    float r = rsqrtf(ss / 1024.f + 1e-6f);
    float sc = lscal[14];
    #pragma unroll
    for (int i = 0; i < 4; i++) {
        int idx = tid + i * 256;
        out[idx] = (g_h2[idx] + pv[i] * r * (1.f + w[idx])) * sc;
    }
}

// ---------------- kv outputs ----------------
__global__ __launch_bounds__(256) void k_copy(float* __restrict__ out,
                                              const float* __restrict__ kv,
                                              const int* __restrict__ pos_ids) {
    int pos = pos_ids[0];
    size_t total = 3145728;
    for (size_t i = (size_t)blockIdx.x * blockDim.x + threadIdx.x; i < total;
         i += (size_t)gridDim.x * blockDim.x) {
        float v;
        if (i < 524288) {
            int j = (int)(i >> 8), d = (int)(i & 255);
            v = (j == pos) ? g_kcur[13][d] : kv[((size_t)13 * 2048 + j) * 512 + d];
        } else if (i < 1048576) {
            size_t t = i - 524288; int j = (int)(t >> 8), d = (int)(t & 255);
            v = (j == pos) ? g_vcur[13][d] : kv[((size_t)28 * 2048 + j) * 512 + d];
        } else if (i < 2097152) {
            size_t t = i - 1048576; int j = (int)(t >> 9), d = (int)(t & 511);
            v = (j == pos) ? g_kcur[14][d] : kv[((size_t)14 * 2048 + j) * 512 + d];
        } else {
            size_t t = i - 2097152; int j = (int)(t >> 9), d = (int)(t & 511);
            v = (j == pos) ? g_vcur[14][d] : kv[((size_t)29 * 2048 + j) * 512 + d];
        }
        out[1024 + i] = v;
    }
}

// ---------------- host ----------------
extern "C" void kernel_launch(void* const* d_in, const int* in_sizes, int n_in,
                              void* d_out, int out_size) {
    const float* embed     = (const float*)d_in[0];
    const float* cos_s     = (const float*)d_in[1];
    const float* sin_s     = (const float*)d_in[2];
    const float* cos_f     = (const float*)d_in[3];
    const float* sin_f     = (const float*)d_in[4];
    const float* ln_in     = (const float*)d_in[5];
    const float* ln_pa     = (const float*)d_in[6];
    const float* ln_pff    = (const float*)d_in[7];
    const float* ln_postff = (const float*)d_in[8];
    const float* ln_ppli   = (const float*)d_in[9];
    const float* qn_w      = (const float*)d_in[10];
    const float* kn_w      = (const float*)d_in[11];
    const float* Wq        = (const float*)d_in[12];
    const float* Wk        = (const float*)d_in[13];
    const float* Wv        = (const float*)d_in[14];
    const float* Wo        = (const float*)d_in[15];
    const float* Wg        = (const float*)d_in[16];
    const float* Wu        = (const float*)d_in[17];
    const float* Wd        = (const float*)d_in[18];
    const float* Wpg       = (const float*)d_in[19];
    const float* Wpp       = (const float*)d_in[20];
    const float* lscal     = (const float*)d_in[21];
    const float* kv        = (const float*)d_in[22];
    const float* plc       = (const float*)d_in[23];
    const float* img       = (const float*)d_in[24];
    const int*   ids       = (const int*)d_in[27];
    const int*   pid       = (const int*)d_in[28];
    float* out = (float*)d_out;

    k_embed<<<1, 256>>>(embed, img, ids);
    for (int l = 0; l < 15; l++) {
        int full = ((l + 1) % 5 == 0);
        int hd = full ? 512 : 256;
        const float* ct = full ? cos_f : cos_s;
        const float* st = full ? sin_f : sin_s;
        k_qkv<<<dim3(10 * hd / 256, 8), 256>>>(Wq, Wk, Wv, ln_in, ln_ppli, lscal, l, hd);
        k_scores<<<256, 256>>>(kv, qn_w, kn_w, ct, st, pid, l, hd);
        k_attnv<<<dim3(16, 8), 256>>>(kv, pid, l, hd);
        if (full) k_wo<256><<<dim3(4, 16), 256>>>(Wo, l, hd);
        else      k_wo<128><<<dim3(4, 16), 256>>>(Wo, l, hd);
        k_ff1<<<dim3(32, 4), 256>>>(Wg, Wu, ln_pa, ln_pff, l);
        k_wd<<<dim3(4, 32), 256>>>(Wd, l);
        k_pli1<<<dim3(1, 16), 256>>>(Wpg, ln_postff, l);
        k_pli2<<<dim3(4, 8), 256>>>(Wpp, plc, l);
    }
    k_final<<<1, 256>>>(out, ln_ppli, lscal);
    if (out_size >= 3146752) k_copy<<<3072, 256>>>(out, kv, pid);
}

// round 7
// speedup vs baseline: 1.0168x; 1.0168x over previous
#include <cuda_runtime.h>
#include <math.h>

// ---------------- scratch (device globals; no allocation) ----------------
__device__ float g_h0[1024];
__device__ float g_h1[1024];
__device__ float g_h2[1024];
__device__ float g_acc_qkv[5120];      // [q:8*hd][k:hd][v:hd]
__device__ float g_scores[8 * 2048];   // [h][j]
__device__ float g_attn_part[16 * 4096]; // [chunk][h*hd+d]
__device__ float g_acc_o[1024];
__device__ float g_acc_gu[8192];       // [g:4096][u:4096]
__device__ float g_acc_mlp[1024];
__device__ float g_acc_pg[256];
__device__ float g_acc_pli[1024];
__device__ float g_kcur[15][512];
__device__ float g_vcur[15][512];

// ---------------- helpers ----------------
__device__ __forceinline__ float blockReduceSum(float v, float* sred) {
    int tid = threadIdx.x;
    #pragma unroll
    for (int o = 16; o; o >>= 1) v += __shfl_xor_sync(0xffffffff, v, o);
    if ((tid & 31) == 0) sred[tid >> 5] = v;
    __syncthreads();
    if (tid == 0) {
        float t = sred[0];
        #pragma unroll
        for (int i = 1; i < 8; i++) t += sred[i];
        sred[0] = t;
    }
    __syncthreads();
    float r = sred[0];
    __syncthreads();
    return r;
}

__device__ __forceinline__ float blockReduceMax(float v, float* sred) {
    int tid = threadIdx.x;
    #pragma unroll
    for (int o = 16; o; o >>= 1) v = fmaxf(v, __shfl_xor_sync(0xffffffff, v, o));
    if ((tid & 31) == 0) sred[tid >> 5] = v;
    __syncthreads();
    if (tid == 0) {
        float t = sred[0];
        #pragma unroll
        for (int i = 1; i < 8; i++) t = fmaxf(t, sred[i]);
        sred[0] = t;
    }
    __syncthreads();
    float r = sred[0];
    __syncthreads();
    return r;
}

__device__ __forceinline__ float gelu_tanh(float x) {
    float x3 = x * x * x;
    return 0.5f * x * (1.f + tanhf(0.7978845608028654f * (x + 0.044715f * x3)));
}

// ---------------- embed ----------------
__global__ __launch_bounds__(256) void k_embed(const float* __restrict__ embed,
                                               const float* __restrict__ img,
                                               const int* __restrict__ ids) {
    __shared__ float sred[9];
    int tid = threadIdx.x;
    int id = ids[0];
    float iv[4];
    float sa = 0.f;
    #pragma unroll
    for (int i = 0; i < 4; i++) { iv[i] = img[tid + i * 256]; sa += fabsf(iv[i]); }
    sa = blockReduceSum(sa, sred);
    bool isimg = sa > 0.f;
    const float* er = embed + (size_t)id * 1024;
    #pragma unroll
    for (int i = 0; i < 4; i++) {
        int idx = tid + i * 256;
        g_h0[idx] = isimg ? iv[i] : er[idx] * 32.0f; // sqrt(1024)=32
    }
    for (int z = tid; z < 5120; z += 256) g_acc_qkv[z] = 0.f;
}

// ---------------- K1: QKV gemv (+ finish previous layer's h) ----------------
__global__ __launch_bounds__(256) void k_qkv(const float* __restrict__ Wq,
                                             const float* __restrict__ Wk,
                                             const float* __restrict__ Wv,
                                             const float* __restrict__ ln_in,
                                             const float* __restrict__ ln_ppli,
                                             const float* __restrict__ lscal,
                                             int l, int hd) {
    __shared__ float xs[1024];
    __shared__ float sred[9];
    int tid = threadIdx.x;
    float h0v[4];
    if (l == 0) {
        #pragma unroll
        for (int i = 0; i < 4; i++) h0v[i] = g_h0[tid + i * 256];
    } else {
        const float* lw = ln_ppli + (size_t)(l - 1) * 1024;
        float pv[4]; float ss = 0.f;
        #pragma unroll
        for (int i = 0; i < 4; i++) { pv[i] = g_acc_pli[tid + i * 256]; ss += pv[i] * pv[i]; }
        ss = blockReduceSum(ss, sred);
        float r = rsqrtf(ss / 1024.f + 1e-6f);
        float sc = lscal[l - 1];
        #pragma unroll
        for (int i = 0; i < 4; i++) {
            int idx = tid + i * 256;
            h0v[i] = (g_h2[idx] + pv[i] * r * (1.f + lw[idx])) * sc;
        }
        if (blockIdx.x == 0 && blockIdx.y == 0)
            #pragma unroll
            for (int i = 0; i < 4; i++) g_h0[tid + i * 256] = h0v[i];
    }
    {
        float ss = 0.f;
        #pragma unroll
        for (int i = 0; i < 4; i++) ss += h0v[i] * h0v[i];
        ss = blockReduceSum(ss, sred);
        float r = rsqrtf(ss / 1024.f + 1e-6f);
        const float* lw = ln_in + (size_t)l * 1024;
        #pragma unroll
        for (int i = 0; i < 4; i++) { int idx = tid + i * 256; xs[idx] = h0v[i] * r * (1.f + lw[idx]); }
    }
    __syncthreads();

    int o = blockIdx.x * 256 + tid;
    int qsize = 8 * hd;
    int lhd = (hd == 512) ? 9 : 8;
    const float* wbase; int stride;
    if (o < qsize) {
        int hh = o >> lhd; int d = o & (hd - 1);
        wbase = Wq + (size_t)l * 1024 * 4096 + hh * 512 + d; stride = 4096;
    } else if (o < qsize + hd) {
        wbase = Wk + (size_t)l * 1024 * 512 + (o - qsize); stride = 512;
    } else {
        wbase = Wv + (size_t)l * 1024 * 512 + (o - qsize - hd); stride = 512;
    }
    int e0 = blockIdx.y * 128;
    const float* wp = wbase + (size_t)e0 * stride;
    float acc = 0.f;
    #pragma unroll 16
    for (int e = 0; e < 128; e++) { acc += xs[e0 + e] * wp[0]; wp += stride; }
    atomicAdd(&g_acc_qkv[o], acc);
}

// ---------------- K2: finalize q/k/v (rms+rope) + scores ----------------
__global__ __launch_bounds__(256) void k_scores(const float* __restrict__ kv,
                                                const float* __restrict__ qn_w,
                                                const float* __restrict__ kn_w,
                                                const float* __restrict__ cost,
                                                const float* __restrict__ sint,
                                                const int* __restrict__ pos_ids,
                                                int l, int hd) {
    __shared__ float qf[8 * 512];
    __shared__ float kc[512];
    __shared__ float vc[512];
    __shared__ float sred[9];
    int tid = threadIdx.x, wid = tid >> 5, lane = tid & 31;
    int pos = pos_ids[0];
    int half = hd >> 1;
    int lhd = (hd == 512) ? 9 : 8;
    const float* cr = cost + (size_t)pos * hd;
    const float* sr = sint + (size_t)pos * hd;

    // zero acc_o for K5's atomics
    { int gt = blockIdx.x * 256 + tid; if (gt < 1024) g_acc_o[gt] = 0.f; }

    // q rms per head (warp wid -> head wid)
    {
        const float* qraw = g_acc_qkv + (size_t)wid * hd;
        float ss = 0.f;
        for (int i = lane; i < hd; i += 32) { float v = qraw[i]; ss += v * v; }
        #pragma unroll
        for (int o = 16; o; o >>= 1) ss += __shfl_xor_sync(0xffffffff, ss, o);
        float r = rsqrtf(ss / (float)hd + 1e-6f);
        const float* qw = qn_w + (size_t)l * 512;
        for (int i = lane; i < hd; i += 32) qf[wid * hd + i] = qraw[i] * r * (1.f + qw[i]);
    }
    // k rms
    {
        float ss = 0.f;
        for (int i = tid; i < hd; i += 256) { float v = g_acc_qkv[8 * hd + i]; ss += v * v; }
        ss = blockReduceSum(ss, sred);
        float r = rsqrtf(ss / (float)hd + 1e-6f);
        const float* kw = kn_w + (size_t)l * 512;
        for (int i = tid; i < hd; i += 256) kc[i] = g_acc_qkv[8 * hd + i] * r * (1.f + kw[i]);
    }
    // v norm
    {
        float ss = 0.f;
        for (int i = tid; i < hd; i += 256) { float v = g_acc_qkv[9 * hd + i]; ss += v * v; }
        ss = blockReduceSum(ss, sred);
        float r = rsqrtf(ss / (float)hd + 1e-6f);
        for (int i = tid; i < hd; i += 256) vc[i] = g_acc_qkv[9 * hd + i] * r;
    }
    __syncthreads();
    // rope q,k (read pairs to regs, sync, write)
    float tq[16]; float tk[2];
    int nq = (8 * hd) / 256;  // 8 or 16
    int nk = hd / 256;        // 1 or 2
    for (int i = 0; i < nq; i++) {
        int idx = tid + i * 256;
        int h = idx >> lhd; int d = idx & (hd - 1);
        float x = qf[idx];
        float rot = (d < half) ? -qf[h * hd + d + half] : qf[h * hd + d - half];
        tq[i] = x * cr[d] + rot * sr[d];
    }
    for (int i = 0; i < nk; i++) {
        int d = tid + i * 256;
        float x = kc[d];
        float rot = (d < half) ? -kc[d + half] : kc[d - half];
        tk[i] = x * cr[d] + rot * sr[d];
    }
    __syncthreads();
    for (int i = 0; i < nq; i++) qf[tid + i * 256] = tq[i];
    for (int i = 0; i < nk; i++) kc[tid + i * 256] = tk[i];
    __syncthreads();
    if (blockIdx.x == 0) {
        for (int i = 0; i < nk; i++) {
            g_kcur[l][tid + i * 256] = kc[tid + i * 256];
            g_vcur[l][tid + i * 256] = vc[tid + i * 256];
        }
    }
    // scores: warp wid handles j = blockIdx.x*8 + wid
    int j = blockIdx.x * 8 + wid;
    if (j <= pos) {
        const float* Kr = (j == pos) ? kc : (kv + ((size_t)l * 2048 + j) * 512);
        float a[8] = {0, 0, 0, 0, 0, 0, 0, 0};
        for (int i = lane; i < hd; i += 32) {
            float kvv = Kr[i];
            #pragma unroll
            for (int h = 0; h < 8; h++) a[h] += qf[h * hd + i] * kvv;
        }
        #pragma unroll
        for (int h = 0; h < 8; h++) {
            float t = a[h];
            #pragma unroll
            for (int o = 16; o; o >>= 1) t += __shfl_xor_sync(0xffffffff, t, o);
            if (lane == 0) g_scores[h * 2048 + j] = t;
        }
    }
}

// ---------------- K4: softmax + weighted V (partials per j-chunk) ----------------
__global__ __launch_bounds__(256) void k_attnv(const float* __restrict__ kv,
                                               const int* __restrict__ pos_ids,
                                               int l, int hd) {
    __shared__ float ps[128];
    __shared__ float sred[9];
    int tid = threadIdx.x;
    int h = blockIdx.y;
    int pos = pos_ids[0];
    const float* sc = g_scores + (size_t)h * 2048;
    // zero acc_gu for K6
    { int gt = (blockIdx.y * gridDim.x + blockIdx.x) * 256 + tid; if (gt < 8192) g_acc_gu[gt] = 0.f; }
    // stats
    float mx = -1e30f;
    for (int j = tid; j <= pos; j += 256) mx = fmaxf(mx, sc[j]);
    mx = blockReduceMax(mx, sred);
    float se = 0.f;
    for (int j = tid; j <= pos; j += 256) se += __expf(sc[j] - mx);
    se = blockReduceSum(se, sred);
    float inv = 1.f / se;

    int j0 = blockIdx.x * 128;
    if (tid < 128) {
        int j = j0 + tid;
        ps[tid] = (j < pos) ? __expf(sc[j] - mx) * inv : 0.f;
    }
    __syncthreads();
    int jend = pos < j0 + 128 ? pos : j0 + 128; // exclusive bound over cache rows (< pos)
    int nj = jend - j0; if (nj < 0) nj = 0;

    const float* Vb = kv + ((size_t)(15 + l) * 2048 + j0) * 512;
    int nd = hd >> 8;  // 1 or 2
    int d0 = tid, d1 = tid + 256;
    float acc0 = 0.f, acc1 = 0.f;
    #pragma unroll 4
    for (int jj = 0; jj < nj; jj++) {
        float p = ps[jj];
        const float* vr = Vb + (size_t)jj * 512;
        acc0 += p * vr[d0];
        if (nd == 2) acc1 += p * vr[d1];
    }
    if (pos >= j0 && pos < j0 + 128) {
        float pp = __expf(sc[pos] - mx) * inv;
        acc0 += pp * g_vcur[l][d0];
        if (nd == 2) acc1 += pp * g_vcur[l][d1];
    }
    float* op = g_attn_part + (size_t)blockIdx.x * 4096;
    op[h * hd + d0] = acc0;
    if (nd == 2) op[h * hd + d1] = acc1;
}

// ---------------- K5: Wo gemv ----------------
template <int CH>
__global__ __launch_bounds__(256) void k_wo(const float* __restrict__ Wo, int l, int hd) {
    __shared__ float xs[4096];
    int tid = threadIdx.x;
    int N = 8 * hd;
    for (int i = tid; i < N; i += 256) {
        float s = 0.f;
        #pragma unroll
        for (int c = 0; c < 16; c++) s += g_attn_part[c * 4096 + i];
        xs[i] = s;
    }
    __syncthreads();
    int o = blockIdx.x * 256 + tid;
    int i0 = blockIdx.y * CH;
    int lhd = (hd == 512) ? 9 : 8;
    int row0 = (i0 >> lhd) * 512 + (i0 & (hd - 1));
    const float* wp = Wo + (size_t)l * 8 * 512 * 1024 + (size_t)row0 * 1024 + o;
    float acc = 0.f;
    #pragma unroll 16
    for (int i = 0; i < CH; i++) { acc += xs[i0 + i] * wp[0]; wp += 1024; }
    atomicAdd(&g_acc_o[o], acc);
    int gt = (blockIdx.y * gridDim.x + blockIdx.x) * 256 + tid;
    if (gt < 1024) g_acc_mlp[gt] = 0.f;
}

// ---------------- K6: FF gate+up gemv ----------------
__global__ __launch_bounds__(256) void k_ff1(const float* __restrict__ Wg,
                                             const float* __restrict__ Wu,
                                             const float* __restrict__ ln_pa,
                                             const float* __restrict__ ln_pff, int l) {
    __shared__ float xs[1024];
    __shared__ float sred[9];
    int tid = threadIdx.x;
    float ov[4], h1v[4];
    float ss = 0.f;
    #pragma unroll
    for (int i = 0; i < 4; i++) { ov[i] = g_acc_o[tid + i * 256]; ss += ov[i] * ov[i]; }
    ss = blockReduceSum(ss, sred);
    float r = rsqrtf(ss / 1024.f + 1e-6f);
    const float* wpa = ln_pa + (size_t)l * 1024;
    #pragma unroll
    for (int i = 0; i < 4; i++) { int idx = tid + i * 256; h1v[i] = g_h0[idx] + ov[i] * r * (1.f + wpa[idx]); }
    if (blockIdx.x == 0 && blockIdx.y == 0)
        #pragma unroll
        for (int i = 0; i < 4; i++) g_h1[tid + i * 256] = h1v[i];
    float s2 = 0.f;
    #pragma unroll
    for (int i = 0; i < 4; i++) s2 += h1v[i] * h1v[i];
    s2 = blockReduceSum(s2, sred);
    float r2 = rsqrtf(s2 / 1024.f + 1e-6f);
    const float* wpf = ln_pff + (size_t)l * 1024;
    #pragma unroll
    for (int i = 0; i < 4; i++) { int idx = tid + i * 256; xs[idx] = h1v[i] * r2 * (1.f + wpf[idx]); }
    __syncthreads();

    int o = blockIdx.x * 256 + tid; // 0..8191
    const float* wb = (o < 4096) ? (Wg + (size_t)l * 1024 * 4096 + o)
                                 : (Wu + (size_t)l * 1024 * 4096 + (o - 4096));
    int e0 = blockIdx.y * 256;
    const float* wp = wb + (size_t)e0 * 4096;
    float acc = 0.f;
    #pragma unroll 16
    for (int e = 0; e < 256; e++) { acc += xs[e0 + e] * wp[0]; wp += 4096; }
    atomicAdd(&g_acc_gu[o], acc);
    int gt = (blockIdx.y * gridDim.x + blockIdx.x) * 256 + tid;
    if (gt < 256) g_acc_pg[gt] = 0.f;
}

// ---------------- K7: FF down gemv ----------------
__global__ __launch_bounds__(256) void k_wd(const float* __restrict__ Wd, int l) {
    __shared__ float xs[4096];
    int tid = threadIdx.x;
    for (int i = tid; i < 4096; i += 256) {
        float gv = g_acc_gu[i], uv = g_acc_gu[4096 + i];
        xs[i] = gelu_tanh(gv) * uv;
    }
    __syncthreads();
    int o = blockIdx.x * 256 + tid;
    int i0 = blockIdx.y * 128;
    const float* wp = Wd + (size_t)l * 4096 * 1024 + (size_t)i0 * 1024 + o;
    float acc = 0.f;
    #pragma unroll 16
    for (int i = 0; i < 128; i++) { acc += xs[i0 + i] * wp[0]; wp += 1024; }
    atomicAdd(&g_acc_mlp[o], acc);
    int gt = (blockIdx.y * gridDim.x + blockIdx.x) * 256 + tid;
    if (gt < 1024) g_acc_pli[gt] = 0.f;
}

// ---------------- K8: PLI gate gemv ----------------
__global__ __launch_bounds__(256) void k_pli1(const float* __restrict__ Wpg,
                                              const float* __restrict__ ln_postff, int l) {
    __shared__ float xs[1024];
    __shared__ float sred[9];
    int tid = threadIdx.x;
    float mv[4];
    float ss = 0.f;
    #pragma unroll
    for (int i = 0; i < 4; i++) { mv[i] = g_acc_mlp[tid + i * 256]; ss += mv[i] * mv[i]; }
    ss = blockReduceSum(ss, sred);
    float r = rsqrtf(ss / 1024.f + 1e-6f);
    const float* w = ln_postff + (size_t)l * 1024;
    #pragma unroll
    for (int i = 0; i < 4; i++) {
        int idx = tid + i * 256;
        float h2 = g_h1[idx] + mv[i] * r * (1.f + w[idx]);
        xs[idx] = h2;
        if (blockIdx.y == 0) g_h2[idx] = h2;  // blockIdx.x is always 0
    }
    __syncthreads();
    int o = tid;
    int e0 = blockIdx.y * 64;
    const float* wp = Wpg + (size_t)l * 1024 * 256 + (size_t)e0 * 256 + o;
    float acc = 0.f;
    #pragma unroll 16
    for (int e = 0; e < 64; e++) { acc += xs[e0 + e] * wp[0]; wp += 256; }
    atomicAdd(&g_acc_pg[o], acc);
    int gt = blockIdx.y * 256 + tid;
    for (int z = gt; z < 5120; z += gridDim.y * 256) g_acc_qkv[z] = 0.f;
}

// ---------------- K9: PLI proj gemv ----------------
__global__ __launch_bounds__(256) void k_pli2(const float* __restrict__ Wpp,
                                              const float* __restrict__ plc, int l) {
    __shared__ float xs[256];
    int tid = threadIdx.x;
    xs[tid] = gelu_tanh(g_acc_pg[tid]) * plc[(size_t)l * 256 + tid];
    __syncthreads();
    int o = blockIdx.x * 256 + tid;
    int e0 = blockIdx.y * 32;
    const float* wp = Wpp + (size_t)l * 256 * 1024 + (size_t)e0 * 1024 + o;
    float acc = 0.f;
    #pragma unroll
    for (int e = 0; e < 32; e++) { acc += xs[e0 + e] * wp[0]; wp += 1024; }
    atomicAdd(&g_acc_pli[o], acc);
}

// ---------------- final h ----------------
__global__ __launch_bounds__(256) void k_final(float* __restrict__ out,
                                               const float* __restrict__ ln_ppli,
                                               const float* __restrict__ lscal) {
    __shared__ float sred[9];
    int tid = threadIdx.x;
    const float* w = ln_ppli + (size_t)14 * 1024;
    float pv[4]; float ss = 0.f;
    #pragma unroll
    for (int i = 0; i < 4; i++) { pv[i] = g_acc_pli[tid + i * 256]; ss += pv[i] * pv[i]; }
    ss = blockReduceSum(ss, sred);
    float r = rsqrtf(ss / 1024.f + 1e-6f);
    float sc = lscal[14];
    #pragma unroll
    for (int i = 0; i < 4; i++) {
        int idx = tid + i * 256;
        out[idx] = (g_h2[idx] + pv[i] * r * (1.f + w[idx])) * sc;
    }
}

// ---------------- kv outputs ----------------
__global__ __launch_bounds__(256) void k_copy(float* __restrict__ out,
                                              const float* __restrict__ kv,
                                              const int* __restrict__ pos_ids) {
    int pos = pos_ids[0];
    size_t total = 3145728;
    for (size_t i = (size_t)blockIdx.x * blockDim.x + threadIdx.x; i < total;
         i += (size_t)gridDim.x * blockDim.x) {
        float v;
        if (i < 524288) {
            int j = (int)(i >> 8), d = (int)(i & 255);
            v = (j == pos) ? g_kcur[13][d] : kv[((size_t)13 * 2048 + j) * 512 + d];
        } else if (i < 1048576) {
            size_t t = i - 524288; int j = (int)(t >> 8), d = (int)(t & 255);
            v = (j == pos) ? g_vcur[13][d] : kv[((size_t)28 * 2048 + j) * 512 + d];
        } else if (i < 2097152) {
            size_t t = i - 1048576; int j = (int)(t >> 9), d = (int)(t & 511);
            v = (j == pos) ? g_kcur[14][d] : kv[((size_t)14 * 2048 + j) * 512 + d];
        } else {
            size_t t = i - 2097152; int j = (int)(t >> 9), d = (int)(t & 511);
            v = (j == pos) ? g_vcur[14][d] : kv[((size_t)29 * 2048 + j) * 512 + d];
        }
        out[1024 + i] = v;
    }
}

// ---------------- host ----------------
extern "C" void kernel_launch(void* const* d_in, const int* in_sizes, int n_in,
                              void* d_out, int out_size) {
    const float* embed     = (const float*)d_in[0];
    const float* cos_s     = (const float*)d_in[1];
    const float* sin_s     = (const float*)d_in[2];
    const float* cos_f     = (const float*)d_in[3];
    const float* sin_f     = (const float*)d_in[4];
    const float* ln_in     = (const float*)d_in[5];
    const float* ln_pa     = (const float*)d_in[6];
    const float* ln_pff    = (const float*)d_in[7];
    const float* ln_postff = (const float*)d_in[8];
    const float* ln_ppli   = (const float*)d_in[9];
    const float* qn_w      = (const float*)d_in[10];
    const float* kn_w      = (const float*)d_in[11];
    const float* Wq        = (const float*)d_in[12];
    const float* Wk        = (const float*)d_in[13];
    const float* Wv        = (const float*)d_in[14];
    const float* Wo        = (const float*)d_in[15];
    const float* Wg        = (const float*)d_in[16];
    const float* Wu        = (const float*)d_in[17];
    const float* Wd        = (const float*)d_in[18];
    const float* Wpg       = (const float*)d_in[19];
    const float* Wpp       = (const float*)d_in[20];
    const float* lscal     = (const float*)d_in[21];
    const float* kv        = (const float*)d_in[22];
    const float* plc       = (const float*)d_in[23];
    const float* img       = (const float*)d_in[24];
    const int*   ids       = (const int*)d_in[27];
    const int*   pid       = (const int*)d_in[28];
    float* out = (float*)d_out;

    k_embed<<<1, 256>>>(embed, img, ids);
    for (int l = 0; l < 15; l++) {
        int full = ((l + 1) % 5 == 0);
        int hd = full ? 512 : 256;
        const float* ct = full ? cos_f : cos_s;
        const float* st = full ? sin_f : sin_s;
        k_qkv<<<dim3(10 * hd / 256, 8), 256>>>(Wq, Wk, Wv, ln_in, ln_ppli, lscal, l, hd);
        k_scores<<<256, 256>>>(kv, qn_w, kn_w, ct, st, pid, l, hd);
        k_attnv<<<dim3(16, 8), 256>>>(kv, pid, l, hd);
        if (full) k_wo<256><<<dim3(4, 16), 256>>>(Wo, l, hd);
        else      k_wo<128><<<dim3(4, 16), 256>>>(Wo, l, hd);
        k_ff1<<<dim3(32, 4), 256>>>(Wg, Wu, ln_pa, ln_pff, l);
        k_wd<<<dim3(4, 32), 256>>>(Wd, l);
        k_pli1<<<dim3(1, 16), 256>>>(Wpg, ln_postff, l);
        k_pli2<<<dim3(4, 8), 256>>>(Wpp, plc, l);
    }
    k_final<<<1, 256>>>(out, ln_ppli, lscal);
    if (out_size >= 3146752) k_copy<<<3072, 256>>>(out, kv, pid);
}